// round 13
// baseline (speedup 1.0000x reference)
#include <cuda_runtime.h>
#include <cuda_bf16.h>
#include <cstdint>

#define NN 100000
#define EE 1600000
#define NT128 ((NN + 127) / 128)   // 782 tiles of 128 rows

typedef uint32_t u32;

// ---------------- scratch (static device globals; no allocations) ----------
__device__ __nv_bfloat16  g_hhi[(NN + 128) * 64];  // final-layer h, bf16 hi
__device__ __nv_bfloat16  g_hlo[(NN + 128) * 64];  // final-layer h, bf16 lo
__device__ float          g_pq0[NN * 128];  // pq ping buffer
__device__ float          g_pq1[NN * 128];  // pq pong buffer
__device__ int            g_src[EE];        // int32 source indices
__device__ unsigned       g_gmax[64];       // global max bits (values >= 0)
__device__ float          g_c128[128];      // head constant: g @ Wa[64:128] + ba
__device__ __nv_bfloat16  g_whi[5 * 128 * 64];  // weight hi parts, [n][k] flat
__device__ __nv_bfloat16  g_wlo[5 * 128 * 64];  // weight lo parts

// ---------------- convert (fused gmax zero + dtype detect) ------------------
__global__ void convert_kernel(const int* __restrict__ ei) {
    __shared__ int s64;
    if (blockIdx.x == 0 && threadIdx.x < 64) g_gmax[threadIdx.x] = 0u;
    if (threadIdx.x == 0) {
        // int64 layout => odd words of src row all zero (0<=src<1e5);
        // int32 layout => P(all 64 zero) ~ 1e-320.
        int z = 0;
        for (int i = 0; i < 64; i++) z += (ei[2 * i + 1] == 0) ? 1 : 0;
        s64 = (z == 64) ? 1 : 0;
    }
    __syncthreads();
    int e = blockIdx.x * blockDim.x + threadIdx.x;
    if (e < EE) g_src[e] = s64 ? ei[2 * e] : ei[e];
}

// ---------------- layer 1: warp-per-node + fused weight prep ---------------
__global__ void layer1_kernel(const float* __restrict__ x,
                              const float* __restrict__ W1,
                              const float* __restrict__ b1,
                              const float* __restrict__ Wl0,
                              const float* __restrict__ Wl1,
                              const float* __restrict__ Wl2,
                              const float* __restrict__ Wl3,
                              const float* __restrict__ Wa) {
    if (blockIdx.x >= 12500) {
        int b = blockIdx.x - 12500;
        const float* W = (b == 0) ? Wl0 : (b == 1) ? Wl1 : (b == 2) ? Wl2
                       : (b == 3) ? Wl3 : Wa;
        for (int i = threadIdx.x; i < 8192; i += 256) {
            int n = i >> 6, k = i & 63;
            float wv;
            if (b < 4)
                wv = (n < 64) ? (W[k * 64 + n] - W[(k + 64) * 64 + n])
                              : W[(k + 64) * 64 + (n - 64)];
            else
                wv = W[k * 128 + n];
            __nv_bfloat16 hi = __float2bfloat16(wv);
            __nv_bfloat16 lo = __float2bfloat16(wv - __bfloat162float(hi));
            g_whi[b * 8192 + i] = hi;
            g_wlo[b * 8192 + i] = lo;
        }
        return;
    }
    __shared__ float sW[384];   // W1: 6 rows x 64
    __shared__ float sb[64];
    int tid = threadIdx.x;
    for (int i = tid; i < 448; i += 256) {
        if (i < 384) sW[i] = W1[i];
        else         sb[i - 384] = b1[i - 384];
    }
    __syncthreads();
    int lane = tid & 31;
    int node = blockIdx.x * 8 + (tid >> 5);
    float xv = (lane < 3) ? x[node * 3 + lane] : 0.f;
    float x0 = __shfl_sync(0xffffffffu, xv, 0);
    float x1 = __shfl_sync(0xffffffffu, xv, 1);
    float x2 = __shfl_sync(0xffffffffu, xv, 2);
    int c = lane * 2;
    float w30 = sW[192 + c], w31 = sW[193 + c];
    float w40 = sW[256 + c], w41 = sW[257 + c];
    float w50 = sW[320 + c], w51 = sW[321 + c];
    float q0 = x0 * w30 + x1 * w40 + x2 * w50;
    float q1 = x0 * w31 + x1 * w41 + x2 * w51;
    float p0 = sb[c]     + x0 * (sW[c] - w30)     + x1 * (sW[64 + c] - w40)
                         + x2 * (sW[128 + c] - w50);
    float p1 = sb[c + 1] + x0 * (sW[c + 1] - w31) + x1 * (sW[65 + c] - w41)
                         + x2 * (sW[129 + c] - w51);
    *(float2*)(g_pq0 + node * 128 + c)      = make_float2(p0, p1);
    *(float2*)(g_pq0 + node * 128 + 64 + c) = make_float2(q0, q1);
}

// ---------------- standalone edge (final layer): pq0 -> g_hhi/lo + gmax -----
__global__ void edge_kernel() {
    __shared__ unsigned sm[64];
    int gw   = (blockIdx.x * blockDim.x + threadIdx.x) >> 5;  // warp: 2 nodes
    int lane = threadIdx.x & 31;
    int half = lane >> 4;
    int hl   = lane & 15;
    int node = gw * 2 + half;
    int s = g_src[gw * 32 + lane];
    float4 m = make_float4(-3.402823466e38f, -3.402823466e38f,
                           -3.402823466e38f, -3.402823466e38f);
    const float* pq = g_pq0;
#pragma unroll
    for (int k = 0; k < 16; k++) {
        int j = __shfl_sync(0xffffffffu, s, (half << 4) + k);
        float4 v = *(const float4*)(pq + j * 128 + 64 + hl * 4);
        m.x = fmaxf(m.x, v.x);
        m.y = fmaxf(m.y, v.y);
        m.z = fmaxf(m.z, v.z);
        m.w = fmaxf(m.w, v.w);
    }
    float4 p = *(const float4*)(pq + node * 128 + hl * 4);
    float r0 = fmaxf(p.x + m.x, 0.f);
    float r1 = fmaxf(p.y + m.y, 0.f);
    float r2 = fmaxf(p.z + m.z, 0.f);
    float r3 = fmaxf(p.w + m.w, 0.f);
    __nv_bfloat16 h0 = __float2bfloat16(r0), h1 = __float2bfloat16(r1);
    __nv_bfloat16 h2 = __float2bfloat16(r2), h3 = __float2bfloat16(r3);
    __nv_bfloat16 l0 = __float2bfloat16(r0 - __bfloat162float(h0));
    __nv_bfloat16 l1 = __float2bfloat16(r1 - __bfloat162float(h1));
    __nv_bfloat16 l2 = __float2bfloat16(r2 - __bfloat162float(h2));
    __nv_bfloat16 l3 = __float2bfloat16(r3 - __bfloat162float(h3));
    __nv_bfloat162 hp0 = __halves2bfloat162(h0, h1);
    __nv_bfloat162 hp1 = __halves2bfloat162(h2, h3);
    __nv_bfloat162 lp0 = __halves2bfloat162(l0, l1);
    __nv_bfloat162 lp1 = __halves2bfloat162(l2, l3);
    uint2 hv = make_uint2(*(u32*)&hp0, *(u32*)&hp1);
    uint2 lv = make_uint2(*(u32*)&lp0, *(u32*)&lp1);
    *(uint2*)(g_hhi + node * 64 + hl * 4) = hv;
    *(uint2*)(g_hlo + node * 64 + hl * 4) = lv;
    if (threadIdx.x < 64) sm[threadIdx.x] = 0u;
    __syncthreads();
    atomicMax(&sm[hl * 4 + 0], __float_as_uint(r0));   // r >= 0
    atomicMax(&sm[hl * 4 + 1], __float_as_uint(r1));
    atomicMax(&sm[hl * 4 + 2], __float_as_uint(r2));
    atomicMax(&sm[hl * 4 + 3], __float_as_uint(r3));
    __syncthreads();
    if (threadIdx.x < 64) atomicMax(&g_gmax[threadIdx.x], sm[threadIdx.x]);
}

// ---------------- mma / ldmatrix / cp.async helpers -------------------------
static __device__ __forceinline__ void mma16816(float d[4], const u32 a[4],
                                                const u32 b[2]) {
    asm volatile(
        "mma.sync.aligned.m16n8k16.row.col.f32.bf16.bf16.f32 "
        "{%0,%1,%2,%3}, {%4,%5,%6,%7}, {%8,%9}, {%0,%1,%2,%3};"
        : "+f"(d[0]), "+f"(d[1]), "+f"(d[2]), "+f"(d[3])
        : "r"(a[0]), "r"(a[1]), "r"(a[2]), "r"(a[3]), "r"(b[0]), "r"(b[1]));
}
static __device__ __forceinline__ void ldsm4(u32 r[4], u32 addr) {
    asm volatile("ldmatrix.sync.aligned.m8n8.x4.shared.b16 {%0,%1,%2,%3}, [%4];"
        : "=r"(r[0]), "=r"(r[1]), "=r"(r[2]), "=r"(r[3]) : "r"(addr));
}
static __device__ __forceinline__ u32 smem_u32(const void* p) {
    u32 a;
    asm("{ .reg .u64 t; cvta.to.shared.u64 t, %1; cvt.u32.u64 %0, t; }"
        : "=r"(a) : "l"(p));
    return a;
}
static __device__ __forceinline__ void cpasync16(u32 dst, const void* src) {
    asm volatile("cp.async.cg.shared.global [%0], [%1], 16;"
        :: "r"(dst), "l"(src) : "memory");
}
static __device__ __forceinline__ void cpasync_wait_all() {
    asm volatile("cp.async.commit_group;\n\tcp.async.wait_group 0;" ::: "memory");
}

// ---------------- FUSED edge + GEMM: pqin -> edge -> h @ Wc -> pqout --------
// Per CTA (128 nodes x 128 cols): gather q rows for the tile's 16-NN edge max,
// compute h = relu(p + max q[src]) in registers, split bf16 hi/lo DIRECTLY
// into the smem A buffer (h never touches gmem), then the R12 mma + epilogue.
// B streams in via cp.async concurrently with the gather. Ping-pong pq
// buffers remove the in-place hazard (other CTAs still read old q).
// smem: Bhi[128][72]@0, Blo@18432, Ahi[128][72]@36864, Alo@55296,
//       bias@73728. Total 74240 B, 3 CTAs/SM.
__global__ void __launch_bounds__(256, 3) egemm_kernel(int layer,
                                                       const float* __restrict__ bias,
                                                       int inparity) {
    extern __shared__ unsigned char smem[];
    float* sB = (float*)(smem + 73728);
    int tid = threadIdx.x;
    int lane = tid & 31;
    int wid  = tid >> 5;
    int nb  = blockIdx.x * 128;
    u32 sbase = smem_u32(smem);
    const float* pqin  = inparity ? g_pq1 : g_pq0;
    float*       pqout = inparity ? g_pq0 : g_pq1;

    // B: 128 rows x 8 chunks x {hi,lo} = 2048 chunks (async, overlaps gather)
    {
        const char* wh = (const char*)(g_whi + layer * 8192);
        const char* wl = (const char*)(g_wlo + layer * 8192);
#pragma unroll
        for (int c = tid; c < 2048; c += 256) {
            int half = c >> 10, idx = c & 1023;
            u32 off = (u32)(idx >> 3) * 144 + (u32)(idx & 7) * 16;
            cpasync16(sbase + half * 18432 + off,
                      (half ? wl : wh) + idx * 16);
        }
    }
    if (tid < 128) sB[tid] = (tid < 64) ? bias[tid] : 0.f;

    // EDGE phase: each warp produces 16 h rows (2 nodes/iter x 8 iters)
    {
        int half = lane >> 4;
        int hl   = lane & 15;
#pragma unroll 1
        for (int it = 0; it < 8; it++) {
            int base = nb + wid * 16 + it * 2;   // node pair
            int node = base + half;
            int sidx = base * 16 + lane;
            int s = (sidx < EE) ? g_src[sidx] : 0;
            float4 m = make_float4(-3.402823466e38f, -3.402823466e38f,
                                   -3.402823466e38f, -3.402823466e38f);
#pragma unroll
            for (int k = 0; k < 16; k++) {
                int j = __shfl_sync(0xffffffffu, s, (half << 4) + k);
                float4 v = *(const float4*)(pqin + j * 128 + 64 + hl * 4);
                m.x = fmaxf(m.x, v.x);
                m.y = fmaxf(m.y, v.y);
                m.z = fmaxf(m.z, v.z);
                m.w = fmaxf(m.w, v.w);
            }
            float4 p = (node < NN) ? *(const float4*)(pqin + node * 128 + hl * 4)
                                   : make_float4(0.f, 0.f, 0.f, 0.f);
            float r0 = fmaxf(p.x + m.x, 0.f);
            float r1 = fmaxf(p.y + m.y, 0.f);
            float r2 = fmaxf(p.z + m.z, 0.f);
            float r3 = fmaxf(p.w + m.w, 0.f);
            __nv_bfloat16 h0 = __float2bfloat16(r0), h1 = __float2bfloat16(r1);
            __nv_bfloat16 h2 = __float2bfloat16(r2), h3 = __float2bfloat16(r3);
            __nv_bfloat16 l0 = __float2bfloat16(r0 - __bfloat162float(h0));
            __nv_bfloat16 l1 = __float2bfloat16(r1 - __bfloat162float(h1));
            __nv_bfloat16 l2 = __float2bfloat16(r2 - __bfloat162float(h2));
            __nv_bfloat16 l3 = __float2bfloat16(r3 - __bfloat162float(h3));
            __nv_bfloat162 hp0 = __halves2bfloat162(h0, h1);
            __nv_bfloat162 hp1 = __halves2bfloat162(h2, h3);
            __nv_bfloat162 lp0 = __halves2bfloat162(l0, l1);
            __nv_bfloat162 lp1 = __halves2bfloat162(l2, l3);
            int lrow = wid * 16 + it * 2 + half;
            *(uint2*)(smem + 36864 + lrow * 144 + hl * 8) =
                make_uint2(*(u32*)&hp0, *(u32*)&hp1);
            *(uint2*)(smem + 55296 + lrow * 144 + hl * 8) =
                make_uint2(*(u32*)&lp0, *(u32*)&lp1);
        }
    }
    cpasync_wait_all();
    __syncthreads();

    // GEMM phase (identical structure to R12 mode 0)
    int wm = wid & 3;      // rows wm*32..+32
    int wn = wid >> 2;     // cols wn*64..+64
    int brow = wn * 64 + (lane & 7) + ((lane >> 4) << 3);
    u32 bHi = sbase + (brow * 72 + ((lane >> 3) & 1) * 8) * 2;
    u32 bLo = bHi + 18432;
    int r = lane >> 2, q = lane & 3;

#pragma unroll
    for (int mt = 0; mt < 2; mt++) {
        u32 aHi = sbase + 36864 +
                  ((wm * 32 + mt * 16 + (lane & 15)) * 72 + (lane >> 4) * 8) * 2;
        u32 aLo = aHi + 18432;

        float d[8][4];
#pragma unroll
        for (int nf = 0; nf < 8; nf++)
#pragma unroll
            for (int j = 0; j < 4; j++) d[nf][j] = 0.f;

#pragma unroll
        for (int kk = 0; kk < 4; kk++) {
            int ko = kk * 32;
            u32 ah[4], al[4], bb[4][4];
            ldsm4(ah, aHi + ko);
            ldsm4(al, aLo + ko);
#pragma unroll
            for (int p2 = 0; p2 < 4; p2++) ldsm4(bb[p2], bHi + p2 * 2304 + ko);
#pragma unroll
            for (int nf = 0; nf < 8; nf++)
                mma16816(d[nf], ah, &bb[nf >> 1][(nf & 1) * 2]);
#pragma unroll
            for (int nf = 0; nf < 8; nf++)
                mma16816(d[nf], al, &bb[nf >> 1][(nf & 1) * 2]);
#pragma unroll
            for (int p2 = 0; p2 < 4; p2++) ldsm4(bb[p2], bLo + p2 * 2304 + ko);
#pragma unroll
            for (int nf = 0; nf < 8; nf++)
                mma16816(d[nf], ah, &bb[nf >> 1][(nf & 1) * 2]);
        }

        int row0 = nb + wm * 32 + mt * 16 + r;
#pragma unroll
        for (int nf = 0; nf < 8; nf++) {
            int gcol = wn * 64 + nf * 8 + 2 * q;
            float bx = sB[gcol], by = sB[gcol + 1];
            float2 v0 = make_float2(d[nf][0] + bx, d[nf][1] + by);
            float2 v1 = make_float2(d[nf][2] + bx, d[nf][3] + by);
            if (row0 < NN)     *(float2*)(pqout + row0 * 128 + gcol)       = v0;
            if (row0 + 8 < NN) *(float2*)(pqout + (row0 + 8) * 128 + gcol) = v1;
        }
    }
}

// ---------------- head GEMM (mode-1 of R12): g_hhi/lo @ Wa + fused head -----
// smem: Bhi@0, Blo@18432, Ahi@36864, Alo@55296, bias@73728, Wb@74240.
__global__ void __launch_bounds__(256, 3) head_gemm_kernel(const float* __restrict__ Wb,
                                                           float* __restrict__ out) {
    extern __shared__ unsigned char smem[];
    float* sB  = (float*)(smem + 73728);
    float* sWb = (float*)(smem + 74240);
    int tid = threadIdx.x;
    int nb  = blockIdx.x * 128;
    u32 sbase = smem_u32(smem);

    {
        const char* wh = (const char*)(g_whi + 4 * 8192);
        const char* wl = (const char*)(g_wlo + 4 * 8192);
#pragma unroll
        for (int c = tid; c < 2048; c += 256) {
            int half = c >> 10, idx = c & 1023;
            u32 off = (u32)(idx >> 3) * 144 + (u32)(idx & 7) * 16;
            cpasync16(sbase + half * 18432 + off,
                      (half ? wl : wh) + idx * 16);
        }
    }
    {
        const char* ah = (const char*)(g_hhi + (size_t)nb * 64);
        const char* al = (const char*)(g_hlo + (size_t)nb * 64);
#pragma unroll
        for (int c = tid; c < 2048; c += 256) {
            int half = c >> 10, idx = c & 1023;
            u32 off = (u32)(idx >> 3) * 144 + (u32)(idx & 7) * 16;
            cpasync16(sbase + 36864 + half * 18432 + off,
                      (half ? al : ah) + idx * 16);
        }
    }
    if (tid < 128) sB[tid] = g_c128[tid];
    for (int i = tid; i < 384; i += 256) sWb[i] = Wb[i];
    cpasync_wait_all();
    __syncthreads();

    int lane = tid & 31;
    int wid  = tid >> 5;
    int wm   = wid & 3;
    int wn   = wid >> 2;
    int brow = wn * 64 + (lane & 7) + ((lane >> 4) << 3);
    u32 bHi = sbase + (brow * 72 + ((lane >> 3) & 1) * 8) * 2;
    u32 bLo = bHi + 18432;
    int r = lane >> 2, q = lane & 3;

#pragma unroll
    for (int mt = 0; mt < 2; mt++) {
        u32 aHi = sbase + 36864 +
                  ((wm * 32 + mt * 16 + (lane & 15)) * 72 + (lane >> 4) * 8) * 2;
        u32 aLo = aHi + 18432;

        float d[8][4];
#pragma unroll
        for (int nf = 0; nf < 8; nf++)
#pragma unroll
            for (int j = 0; j < 4; j++) d[nf][j] = 0.f;

#pragma unroll
        for (int kk = 0; kk < 4; kk++) {
            int ko = kk * 32;
            u32 ah[4], al[4], bb[4][4];
            ldsm4(ah, aHi + ko);
            ldsm4(al, aLo + ko);
#pragma unroll
            for (int p2 = 0; p2 < 4; p2++) ldsm4(bb[p2], bHi + p2 * 2304 + ko);
#pragma unroll
            for (int nf = 0; nf < 8; nf++)
                mma16816(d[nf], ah, &bb[nf >> 1][(nf & 1) * 2]);
#pragma unroll
            for (int nf = 0; nf < 8; nf++)
                mma16816(d[nf], al, &bb[nf >> 1][(nf & 1) * 2]);
#pragma unroll
            for (int p2 = 0; p2 < 4; p2++) ldsm4(bb[p2], bLo + p2 * 2304 + ko);
#pragma unroll
            for (int nf = 0; nf < 8; nf++)
                mma16816(d[nf], ah, &bb[nf >> 1][(nf & 1) * 2]);
        }

        int row0 = nb + wm * 32 + mt * 16 + r;
        float o0[3] = {0.f, 0.f, 0.f};
        float o1[3] = {0.f, 0.f, 0.f};
#pragma unroll
        for (int nf = 0; nf < 8; nf++) {
            int gcol = wn * 64 + nf * 8 + 2 * q;
            float bx = sB[gcol], by = sB[gcol + 1];
            float v00 = fmaxf(d[nf][0] + bx, 0.f);
            float v01 = fmaxf(d[nf][1] + by, 0.f);
            float v10 = fmaxf(d[nf][2] + bx, 0.f);
            float v11 = fmaxf(d[nf][3] + by, 0.f);
#pragma unroll
            for (int c = 0; c < 3; c++) {
                float wb0 = sWb[gcol * 3 + c];
                float wb1 = sWb[(gcol + 1) * 3 + c];
                o0[c] += v00 * wb0 + v01 * wb1;
                o1[c] += v10 * wb0 + v11 * wb1;
            }
        }
#pragma unroll
        for (int msk = 1; msk <= 2; msk <<= 1) {
#pragma unroll
            for (int c = 0; c < 3; c++) {
                o0[c] += __shfl_xor_sync(0xffffffffu, o0[c], msk);
                o1[c] += __shfl_xor_sync(0xffffffffu, o1[c], msk);
            }
        }
        if (q == 0) {
#pragma unroll
            for (int c = 0; c < 3; c++) {
                if (row0 < NN)     atomicAdd(out + row0 * 3 + c,       o0[c]);
                if (row0 + 8 < NN) atomicAdd(out + (row0 + 8) * 3 + c, o1[c]);
            }
        }
    }
}

// ---------------- c128 (block 0) + out init (blocks 1..) --------------------
__global__ void c128_kernel(const float* __restrict__ Wa,
                            const float* __restrict__ ba,
                            const float* __restrict__ bb,
                            const float* __restrict__ x,
                            float* __restrict__ out) {
    if (blockIdx.x == 0) {
        int t = threadIdx.x;
        if (t < 128) {
            float s = ba[t];
#pragma unroll 8
            for (int c = 0; c < 64; c++)
                s += __uint_as_float(g_gmax[c]) * Wa[(64 + c) * 128 + t];
            g_c128[t] = s;
        }
        return;
    }
    int idx = (blockIdx.x - 1) * 256 + threadIdx.x;
    if (idx < NN * 3) {
        int c = idx - (idx / 3) * 3;
        out[idx] = x[idx] + bb[c];
    }
}

// ---------------- launch ----------------------------------------------------
extern "C" void kernel_launch(void* const* d_in, const int* in_sizes, int n_in,
                              void* d_out, int out_size) {
    (void)in_sizes; (void)n_in; (void)out_size;
    const float* x  = (const float*)d_in[0];
    const int*   ei = (const int*)d_in[1];
    const float* W1 = (const float*)d_in[2];
    const float* b1 = (const float*)d_in[3];
    const float* Wl[4] = {(const float*)d_in[4], (const float*)d_in[6],
                          (const float*)d_in[8], (const float*)d_in[10]};
    const float* bl[4] = {(const float*)d_in[5], (const float*)d_in[7],
                          (const float*)d_in[9], (const float*)d_in[11]};
    const float* Wa = (const float*)d_in[12];
    const float* ba = (const float*)d_in[13];
    const float* Wb = (const float*)d_in[14];
    const float* bb = (const float*)d_in[15];
    float* out = (float*)d_out;

    const int EG_SMEM = 74240;
    const int HG_SMEM = 75776;
    static bool attr_set = false;
    if (!attr_set) {
        cudaFuncSetAttribute(egemm_kernel,
                             cudaFuncAttributeMaxDynamicSharedMemorySize, EG_SMEM);
        cudaFuncSetAttribute(head_gemm_kernel,
                             cudaFuncAttributeMaxDynamicSharedMemorySize, HG_SMEM);
        attr_set = true;
    }

    convert_kernel<<<(EE + 255) / 256, 256>>>(ei);                        // #1
    layer1_kernel<<<12505, 256>>>(x, W1, b1, Wl[0], Wl[1], Wl[2], Wl[3], Wa); // #2

    // fused edge+GEMM layers (ping-pong pq buffers)
    for (int l = 0; l < 4; l++)
        egemm_kernel<<<NT128, 256, EG_SMEM>>>(l, bl[l], l & 1);           // #3-#6

    edge_kernel<<<(NN * 16) / 256, 256>>>();                              // #7
    c128_kernel<<<1 + (NN * 3 + 255) / 256, 256>>>(Wa, ba, bb, x, out);   // #8
    head_gemm_kernel<<<NT128, 256, HG_SMEM>>>(Wb, out);                   // #9
}

// round 14
// speedup vs baseline: 1.1954x; 1.1954x over previous
#include <cuda_runtime.h>
#include <cuda_bf16.h>
#include <cstdint>

#define NN 100000
#define EE 1600000
#define NT128 ((NN + 127) / 128)   // 782 tiles of 128 rows

typedef uint32_t u32;

// ---------------- scratch (static device globals; no allocations) ----------
__device__ __nv_bfloat16  g_hhi[(NN + 128) * 64];  // node features, bf16 hi part
__device__ __nv_bfloat16  g_hlo[(NN + 128) * 64];  // node features, bf16 lo part
__device__ float          g_pq[NN * 128];  // p (cols 0-63), q (cols 64-127)
__device__ int            g_src[EE];       // int32 source indices
__device__ unsigned       g_gmax[64];      // global max bits (values >= 0)
__device__ float          g_c128[128];     // head constant: g @ Wa[64:128] + ba
__device__ __nv_bfloat16  g_whi[5 * 128 * 64];  // weight hi parts, [n][k] flat
__device__ __nv_bfloat16  g_wlo[5 * 128 * 64];  // weight lo parts

// ---------------- convert (fused gmax zero + dtype detect) ------------------
__global__ void convert_kernel(const int* __restrict__ ei) {
    __shared__ int s64;
    if (blockIdx.x == 0 && threadIdx.x < 64) g_gmax[threadIdx.x] = 0u;
    if (threadIdx.x == 0) {
        // int64 layout => odd words of src row all zero (0<=src<1e5);
        // int32 layout => P(all 64 zero) ~ 1e-320.
        int z = 0;
        for (int i = 0; i < 64; i++) z += (ei[2 * i + 1] == 0) ? 1 : 0;
        s64 = (z == 64) ? 1 : 0;
    }
    __syncthreads();
    int e = blockIdx.x * blockDim.x + threadIdx.x;
    if (e < EE) g_src[e] = s64 ? ei[2 * e] : ei[e];
}

// ---------------- layer 1: warp-per-node + fused weight prep ---------------
__global__ void layer1_kernel(const float* __restrict__ x,
                              const float* __restrict__ W1,
                              const float* __restrict__ b1,
                              const float* __restrict__ Wl0,
                              const float* __restrict__ Wl1,
                              const float* __restrict__ Wl2,
                              const float* __restrict__ Wl3,
                              const float* __restrict__ Wa) {
    if (blockIdx.x >= 12500) {
        int b = blockIdx.x - 12500;
        const float* W = (b == 0) ? Wl0 : (b == 1) ? Wl1 : (b == 2) ? Wl2
                       : (b == 3) ? Wl3 : Wa;
        for (int i = threadIdx.x; i < 8192; i += 256) {
            int n = i >> 6, k = i & 63;
            float wv;
            if (b < 4)
                wv = (n < 64) ? (W[k * 64 + n] - W[(k + 64) * 64 + n])
                              : W[(k + 64) * 64 + (n - 64)];
            else
                wv = W[k * 128 + n];
            __nv_bfloat16 hi = __float2bfloat16(wv);
            __nv_bfloat16 lo = __float2bfloat16(wv - __bfloat162float(hi));
            g_whi[b * 8192 + i] = hi;
            g_wlo[b * 8192 + i] = lo;
        }
        return;
    }
    __shared__ float sW[384];   // W1: 6 rows x 64
    __shared__ float sb[64];
    int tid = threadIdx.x;
    for (int i = tid; i < 448; i += 256) {
        if (i < 384) sW[i] = W1[i];
        else         sb[i - 384] = b1[i - 384];
    }
    __syncthreads();
    int lane = tid & 31;
    int node = blockIdx.x * 8 + (tid >> 5);
    float xv = (lane < 3) ? x[node * 3 + lane] : 0.f;
    float x0 = __shfl_sync(0xffffffffu, xv, 0);
    float x1 = __shfl_sync(0xffffffffu, xv, 1);
    float x2 = __shfl_sync(0xffffffffu, xv, 2);
    int c = lane * 2;
    float w30 = sW[192 + c], w31 = sW[193 + c];
    float w40 = sW[256 + c], w41 = sW[257 + c];
    float w50 = sW[320 + c], w51 = sW[321 + c];
    float q0 = x0 * w30 + x1 * w40 + x2 * w50;
    float q1 = x0 * w31 + x1 * w41 + x2 * w51;
    float p0 = sb[c]     + x0 * (sW[c] - w30)     + x1 * (sW[64 + c] - w40)
                         + x2 * (sW[128 + c] - w50);
    float p1 = sb[c + 1] + x0 * (sW[c + 1] - w31) + x1 * (sW[65 + c] - w41)
                         + x2 * (sW[129 + c] - w51);
    *(float2*)(g_pq + node * 128 + c)      = make_float2(p0, p1);
    *(float2*)(g_pq + node * 128 + 64 + c) = make_float2(q0, q1);
}

// ---------------- edge max: 2 nodes per warp, float4 lanes ------------------
__global__ void edge_kernel(int dogmax) {
    __shared__ unsigned sm[64];
    int gw   = (blockIdx.x * blockDim.x + threadIdx.x) >> 5;  // warp: 2 nodes
    int lane = threadIdx.x & 31;
    int half = lane >> 4;
    int hl   = lane & 15;
    int node = gw * 2 + half;
    int s = g_src[gw * 32 + lane];   // lanes 0-15: node0 srcs, 16-31: node1
    float4 m = make_float4(-3.402823466e38f, -3.402823466e38f,
                           -3.402823466e38f, -3.402823466e38f);
    const float* pq = g_pq;
#pragma unroll
    for (int k = 0; k < 16; k++) {
        int j = __shfl_sync(0xffffffffu, s, (half << 4) + k);
        float4 v = *(const float4*)(pq + j * 128 + 64 + hl * 4);
        m.x = fmaxf(m.x, v.x);
        m.y = fmaxf(m.y, v.y);
        m.z = fmaxf(m.z, v.z);
        m.w = fmaxf(m.w, v.w);
    }
    float4 p = *(const float4*)(pq + node * 128 + hl * 4);
    float r0 = fmaxf(p.x + m.x, 0.f);
    float r1 = fmaxf(p.y + m.y, 0.f);
    float r2 = fmaxf(p.z + m.z, 0.f);
    float r3 = fmaxf(p.w + m.w, 0.f);
    __nv_bfloat16 h0 = __float2bfloat16(r0), h1 = __float2bfloat16(r1);
    __nv_bfloat16 h2 = __float2bfloat16(r2), h3 = __float2bfloat16(r3);
    __nv_bfloat16 l0 = __float2bfloat16(r0 - __bfloat162float(h0));
    __nv_bfloat16 l1 = __float2bfloat16(r1 - __bfloat162float(h1));
    __nv_bfloat16 l2 = __float2bfloat16(r2 - __bfloat162float(h2));
    __nv_bfloat16 l3 = __float2bfloat16(r3 - __bfloat162float(h3));
    __nv_bfloat162 hp0 = __halves2bfloat162(h0, h1);
    __nv_bfloat162 hp1 = __halves2bfloat162(h2, h3);
    __nv_bfloat162 lp0 = __halves2bfloat162(l0, l1);
    __nv_bfloat162 lp1 = __halves2bfloat162(l2, l3);
    uint2 hv = make_uint2(*(u32*)&hp0, *(u32*)&hp1);
    uint2 lv = make_uint2(*(u32*)&lp0, *(u32*)&lp1);
    *(uint2*)(g_hhi + node * 64 + hl * 4) = hv;
    *(uint2*)(g_hlo + node * 64 + hl * 4) = lv;
    if (dogmax) {
        if (threadIdx.x < 64) sm[threadIdx.x] = 0u;
        __syncthreads();
        atomicMax(&sm[hl * 4 + 0], __float_as_uint(r0));   // r >= 0
        atomicMax(&sm[hl * 4 + 1], __float_as_uint(r1));
        atomicMax(&sm[hl * 4 + 2], __float_as_uint(r2));
        atomicMax(&sm[hl * 4 + 3], __float_as_uint(r3));
        __syncthreads();
        if (threadIdx.x < 64) atomicMax(&g_gmax[threadIdx.x], sm[threadIdx.x]);
    }
}

// ---------------- mma / ldmatrix / cp.async helpers -------------------------
static __device__ __forceinline__ void mma16816(float d[4], const u32 a[4],
                                                const u32 b[2]) {
    asm volatile(
        "mma.sync.aligned.m16n8k16.row.col.f32.bf16.bf16.f32 "
        "{%0,%1,%2,%3}, {%4,%5,%6,%7}, {%8,%9}, {%0,%1,%2,%3};"
        : "+f"(d[0]), "+f"(d[1]), "+f"(d[2]), "+f"(d[3])
        : "r"(a[0]), "r"(a[1]), "r"(a[2]), "r"(a[3]), "r"(b[0]), "r"(b[1]));
}
static __device__ __forceinline__ void ldsm4(u32 r[4], u32 addr) {
    asm volatile("ldmatrix.sync.aligned.m8n8.x4.shared.b16 {%0,%1,%2,%3}, [%4];"
        : "=r"(r[0]), "=r"(r[1]), "=r"(r[2]), "=r"(r[3]) : "r"(addr));
}
static __device__ __forceinline__ u32 smem_u32(const void* p) {
    u32 a;
    asm("{ .reg .u64 t; cvta.to.shared.u64 t, %1; cvt.u32.u64 %0, t; }"
        : "=r"(a) : "l"(p));
    return a;
}
static __device__ __forceinline__ void cpasync16(u32 dst, const void* src) {
    asm volatile("cp.async.cg.shared.global [%0], [%1], 16;"
        :: "r"(dst), "l"(src) : "memory");
}
static __device__ __forceinline__ void cpasync_wait_all() {
    asm volatile("cp.async.commit_group;\n\tcp.async.wait_group 0;" ::: "memory");
}

// ---------------- tensor-core GEMM: h[N,64] @ Wc[64,128] --------------------
// R13 experiment: same CTA tile 128M x 128N / grid 782 / same smem+traffic as
// the 26.4us plateau kernel, but 512 threads / 16 warps (warp tile 16M x 64N,
// no M loop) -> 32 accum regs, __launch_bounds__(512,2) = 32 warps/SM (was 24)
// at IDENTICAL memory traffic. Isolates warp-level latency hiding.
// smem: Bhi[128][72]@0, Blo@18432, Ahi[128][72]@36864, Alo@55296,
//       bias@73728 (512B), Wb@74240 (1536B). Total 75776 B.
// mode 0: writes p|q to g_pq; bias on cols 0-63.
// mode 1 (fused head): bias g_c128, relu, out += relu(feat) @ Wb via
//   quad-shfl reduction + atomicAdd (out pre-init to x + bb).
__global__ void __launch_bounds__(512, 2) tc_gemm_kernel(int layer,
                                                         const float* __restrict__ bias,
                                                         int mode,
                                                         const float* __restrict__ Wb,
                                                         float* __restrict__ out) {
    extern __shared__ unsigned char smem[];
    float* sB  = (float*)(smem + 73728);
    float* sWb = (float*)(smem + 74240);
    int tid = threadIdx.x;
    int nb  = blockIdx.x * 128;
    u32 sbase = smem_u32(smem);

    // B: 128 rows x 8 chunks x {hi,lo} = 2048 chunks
    {
        const char* wh = (const char*)(g_whi + layer * 8192);
        const char* wl = (const char*)(g_wlo + layer * 8192);
#pragma unroll
        for (int c = tid; c < 2048; c += 512) {
            int half = c >> 10, idx = c & 1023;
            u32 off = (u32)(idx >> 3) * 144 + (u32)(idx & 7) * 16;
            cpasync16(sbase + half * 18432 + off,
                      (half ? wl : wh) + idx * 16);
        }
    }
    // A: 128 rows x 8 chunks x {hi,lo} = 2048 chunks (gmem oversized past NN)
    {
        const char* ah = (const char*)(g_hhi + (size_t)nb * 64);
        const char* al = (const char*)(g_hlo + (size_t)nb * 64);
#pragma unroll
        for (int c = tid; c < 2048; c += 512) {
            int half = c >> 10, idx = c & 1023;
            u32 off = (u32)(idx >> 3) * 144 + (u32)(idx & 7) * 16;
            cpasync16(sbase + 36864 + half * 18432 + off,
                      (half ? al : ah) + idx * 16);
        }
    }
    if (tid < 128)
        sB[tid] = (mode == 0) ? ((tid < 64) ? bias[tid] : 0.f) : g_c128[tid];
    if (mode == 1 && tid < 384) sWb[tid] = Wb[tid];
    cpasync_wait_all();
    __syncthreads();

    int lane = tid & 31;
    int wid  = tid >> 5;
    int wm   = wid & 7;      // 16-row group: rows wm*16..+16
    int wn   = wid >> 3;     // cols wn*64..+64

    int brow = wn * 64 + (lane & 7) + ((lane >> 4) << 3);
    u32 bHi = sbase + (brow * 72 + ((lane >> 3) & 1) * 8) * 2;
    u32 bLo = bHi + 18432;
    u32 aHi = sbase + 36864 +
              ((wm * 16 + (lane & 15)) * 72 + (lane >> 4) * 8) * 2;
    u32 aLo = aHi + 18432;
    int r = lane >> 2, q = lane & 3;

    float d[8][4];
#pragma unroll
    for (int nf = 0; nf < 8; nf++)
#pragma unroll
        for (int j = 0; j < 4; j++) d[nf][j] = 0.f;

#pragma unroll
    for (int kk = 0; kk < 4; kk++) {
        int ko = kk * 32;
        u32 ah[4], al[4], bb[4][4];
        ldsm4(ah, aHi + ko);
        ldsm4(al, aLo + ko);
#pragma unroll
        for (int p2 = 0; p2 < 4; p2++) ldsm4(bb[p2], bHi + p2 * 2304 + ko);
#pragma unroll
        for (int nf = 0; nf < 8; nf++)
            mma16816(d[nf], ah, &bb[nf >> 1][(nf & 1) * 2]);
#pragma unroll
        for (int nf = 0; nf < 8; nf++)
            mma16816(d[nf], al, &bb[nf >> 1][(nf & 1) * 2]);
#pragma unroll
        for (int p2 = 0; p2 < 4; p2++) ldsm4(bb[p2], bLo + p2 * 2304 + ko);
#pragma unroll
        for (int nf = 0; nf < 8; nf++)
            mma16816(d[nf], ah, &bb[nf >> 1][(nf & 1) * 2]);
    }

    int row0 = nb + wm * 16 + r;
    if (mode == 0) {
#pragma unroll
        for (int nf = 0; nf < 8; nf++) {
            int gcol = wn * 64 + nf * 8 + 2 * q;
            float bx = sB[gcol], by = sB[gcol + 1];
            float2 v0 = make_float2(d[nf][0] + bx, d[nf][1] + by);
            float2 v1 = make_float2(d[nf][2] + bx, d[nf][3] + by);
            if (row0 < NN)     *(float2*)(g_pq + row0 * 128 + gcol)       = v0;
            if (row0 + 8 < NN) *(float2*)(g_pq + (row0 + 8) * 128 + gcol) = v1;
        }
    } else {
        float o0[3] = {0.f, 0.f, 0.f};
        float o1[3] = {0.f, 0.f, 0.f};
#pragma unroll
        for (int nf = 0; nf < 8; nf++) {
            int gcol = wn * 64 + nf * 8 + 2 * q;
            float bx = sB[gcol], by = sB[gcol + 1];
            float v00 = fmaxf(d[nf][0] + bx, 0.f);
            float v01 = fmaxf(d[nf][1] + by, 0.f);
            float v10 = fmaxf(d[nf][2] + bx, 0.f);
            float v11 = fmaxf(d[nf][3] + by, 0.f);
#pragma unroll
            for (int c = 0; c < 3; c++) {
                float wb0 = sWb[gcol * 3 + c];
                float wb1 = sWb[(gcol + 1) * 3 + c];
                o0[c] += v00 * wb0 + v01 * wb1;
                o1[c] += v10 * wb0 + v11 * wb1;
            }
        }
#pragma unroll
        for (int msk = 1; msk <= 2; msk <<= 1) {
#pragma unroll
            for (int c = 0; c < 3; c++) {
                o0[c] += __shfl_xor_sync(0xffffffffu, o0[c], msk);
                o1[c] += __shfl_xor_sync(0xffffffffu, o1[c], msk);
            }
        }
        if (q == 0) {
#pragma unroll
            for (int c = 0; c < 3; c++) {
                if (row0 < NN)     atomicAdd(out + row0 * 3 + c,       o0[c]);
                if (row0 + 8 < NN) atomicAdd(out + (row0 + 8) * 3 + c, o1[c]);
            }
        }
    }
}

// ---------------- c128 (block 0) + out init (blocks 1..) --------------------
__global__ void c128_kernel(const float* __restrict__ Wa,
                            const float* __restrict__ ba,
                            const float* __restrict__ bb,
                            const float* __restrict__ x,
                            float* __restrict__ out) {
    if (blockIdx.x == 0) {
        int t = threadIdx.x;
        if (t < 128) {
            float s = ba[t];
#pragma unroll 8
            for (int c = 0; c < 64; c++)
                s += __uint_as_float(g_gmax[c]) * Wa[(64 + c) * 128 + t];
            g_c128[t] = s;
        }
        return;
    }
    int idx = (blockIdx.x - 1) * 256 + threadIdx.x;
    if (idx < NN * 3) {
        int c = idx - (idx / 3) * 3;
        out[idx] = x[idx] + bb[c];
    }
}

// ---------------- launch ----------------------------------------------------
extern "C" void kernel_launch(void* const* d_in, const int* in_sizes, int n_in,
                              void* d_out, int out_size) {
    (void)in_sizes; (void)n_in; (void)out_size;
    const float* x  = (const float*)d_in[0];
    const int*   ei = (const int*)d_in[1];
    const float* W1 = (const float*)d_in[2];
    const float* b1 = (const float*)d_in[3];
    const float* Wl[4] = {(const float*)d_in[4], (const float*)d_in[6],
                          (const float*)d_in[8], (const float*)d_in[10]};
    const float* bl[4] = {(const float*)d_in[5], (const float*)d_in[7],
                          (const float*)d_in[9], (const float*)d_in[11]};
    const float* Wa = (const float*)d_in[12];
    const float* ba = (const float*)d_in[13];
    const float* Wb = (const float*)d_in[14];
    const float* bb = (const float*)d_in[15];
    float* out = (float*)d_out;

    const int GEMM_SMEM = 75776;
    static bool attr_set = false;
    if (!attr_set) {
        cudaFuncSetAttribute(tc_gemm_kernel,
                             cudaFuncAttributeMaxDynamicSharedMemorySize,
                             GEMM_SMEM);
        attr_set = true;
    }

    convert_kernel<<<(EE + 255) / 256, 256>>>(ei);                        // #1
    layer1_kernel<<<12505, 256>>>(x, W1, b1, Wl[0], Wl[1], Wl[2], Wl[3], Wa); // #2
    edge_kernel<<<(NN * 16) / 256, 256>>>(0);                             // #3

    for (int l = 0; l < 4; l++) {
        tc_gemm_kernel<<<NT128, 512, GEMM_SMEM>>>(l, bl[l], 0, nullptr, nullptr);
        edge_kernel<<<(NN * 16) / 256, 256>>>(l == 3 ? 1 : 0);
    }

    // c128 + out = x + bb init (must precede fused GEMM-5)
    c128_kernel<<<1 + (NN * 3 + 255) / 256, 256>>>(Wa, ba, bb, x, out);
    // GEMM-5 with fused head: out += relu(h@Wa[0:64] + c128) @ Wb
    tc_gemm_kernel<<<NT128, 512, GEMM_SMEM>>>(4, nullptr, 1, Wb, out);
}

// round 15
// speedup vs baseline: 1.4121x; 1.1813x over previous
#include <cuda_runtime.h>
#include <cuda_bf16.h>
#include <cuda_fp16.h>
#include <cstdint>

#define NN 100000
#define EE 1600000
#define NT128 ((NN + 127) / 128)   // 782 tiles of 128 rows

typedef uint32_t u32;

// ---------------- scratch (static device globals; no allocations) ----------
__device__ __nv_bfloat16  g_hhi[(NN + 128) * 64];  // node features, bf16 hi part
__device__ __nv_bfloat16  g_hlo[(NN + 128) * 64];  // node features, bf16 lo part
__device__ float          g_p[(NN + 128) * 64];    // p (f32)
__device__ __half         g_q[(NN + 128) * 64];    // q (fp16 — gather-traffic cut)
__device__ int            g_src[EE];       // int32 source indices
__device__ unsigned       g_gmax[64];      // global max bits (values >= 0)
__device__ float          g_c128[128];     // head constant: g @ Wa[64:128] + ba
__device__ __nv_bfloat16  g_whi[5 * 128 * 64];  // weight hi parts, [n][k] flat
__device__ __nv_bfloat16  g_wlo[5 * 128 * 64];  // weight lo parts

// ---------------- convert (fused gmax zero + dtype detect) ------------------
__global__ void convert_kernel(const int* __restrict__ ei) {
    __shared__ int s64;
    if (blockIdx.x == 0 && threadIdx.x < 64) g_gmax[threadIdx.x] = 0u;
    if (threadIdx.x == 0) {
        // int64 layout => odd words of src row all zero (0<=src<1e5);
        // int32 layout => P(all 64 zero) ~ 1e-320.
        int z = 0;
        for (int i = 0; i < 64; i++) z += (ei[2 * i + 1] == 0) ? 1 : 0;
        s64 = (z == 64) ? 1 : 0;
    }
    __syncthreads();
    int e = blockIdx.x * blockDim.x + threadIdx.x;
    if (e < EE) g_src[e] = s64 ? ei[2 * e] : ei[e];
}

// ---------------- layer 1: warp-per-node + fused weight prep ---------------
__global__ void layer1_kernel(const float* __restrict__ x,
                              const float* __restrict__ W1,
                              const float* __restrict__ b1,
                              const float* __restrict__ Wl0,
                              const float* __restrict__ Wl1,
                              const float* __restrict__ Wl2,
                              const float* __restrict__ Wl3,
                              const float* __restrict__ Wa) {
    if (blockIdx.x >= 12500) {
        int b = blockIdx.x - 12500;
        const float* W = (b == 0) ? Wl0 : (b == 1) ? Wl1 : (b == 2) ? Wl2
                       : (b == 3) ? Wl3 : Wa;
        for (int i = threadIdx.x; i < 8192; i += 256) {
            int n = i >> 6, k = i & 63;
            float wv;
            if (b < 4)
                wv = (n < 64) ? (W[k * 64 + n] - W[(k + 64) * 64 + n])
                              : W[(k + 64) * 64 + (n - 64)];
            else
                wv = W[k * 128 + n];
            __nv_bfloat16 hi = __float2bfloat16(wv);
            __nv_bfloat16 lo = __float2bfloat16(wv - __bfloat162float(hi));
            g_whi[b * 8192 + i] = hi;
            g_wlo[b * 8192 + i] = lo;
        }
        return;
    }
    __shared__ float sW[384];   // W1: 6 rows x 64
    __shared__ float sb[64];
    int tid = threadIdx.x;
    for (int i = tid; i < 448; i += 256) {
        if (i < 384) sW[i] = W1[i];
        else         sb[i - 384] = b1[i - 384];
    }
    __syncthreads();
    int lane = tid & 31;
    int node = blockIdx.x * 8 + (tid >> 5);
    float xv = (lane < 3) ? x[node * 3 + lane] : 0.f;
    float x0 = __shfl_sync(0xffffffffu, xv, 0);
    float x1 = __shfl_sync(0xffffffffu, xv, 1);
    float x2 = __shfl_sync(0xffffffffu, xv, 2);
    int c = lane * 2;
    float w30 = sW[192 + c], w31 = sW[193 + c];
    float w40 = sW[256 + c], w41 = sW[257 + c];
    float w50 = sW[320 + c], w51 = sW[321 + c];
    float q0 = x0 * w30 + x1 * w40 + x2 * w50;
    float q1 = x0 * w31 + x1 * w41 + x2 * w51;
    float p0 = sb[c]     + x0 * (sW[c] - w30)     + x1 * (sW[64 + c] - w40)
                         + x2 * (sW[128 + c] - w50);
    float p1 = sb[c + 1] + x0 * (sW[c + 1] - w31) + x1 * (sW[65 + c] - w41)
                         + x2 * (sW[129 + c] - w51);
    *(float2*)(g_p + node * 64 + c) = make_float2(p0, p1);
    __half2 qh = __floats2half2_rn(q0, q1);
    *(__half2*)(g_q + node * 64 + c) = qh;
}

// ---------------- edge max: 2 nodes per warp, fp16 q gather -----------------
__global__ void edge_kernel(int dogmax) {
    __shared__ unsigned sm[64];
    int gw   = (blockIdx.x * blockDim.x + threadIdx.x) >> 5;  // warp: 2 nodes
    int lane = threadIdx.x & 31;
    int half = lane >> 4;
    int hl   = lane & 15;
    int node = gw * 2 + half;
    int s = g_src[gw * 32 + lane];   // lanes 0-15: node0 srcs, 16-31: node1
    float4 m = make_float4(-3.402823466e38f, -3.402823466e38f,
                           -3.402823466e38f, -3.402823466e38f);
#pragma unroll
    for (int k = 0; k < 16; k++) {
        int j = __shfl_sync(0xffffffffu, s, (half << 4) + k);
        uint2 qv = *(const uint2*)(g_q + j * 64 + hl * 4);   // 4 halves
        float2 v01 = __half22float2(*(__half2*)&qv.x);
        float2 v23 = __half22float2(*(__half2*)&qv.y);
        m.x = fmaxf(m.x, v01.x);
        m.y = fmaxf(m.y, v01.y);
        m.z = fmaxf(m.z, v23.x);
        m.w = fmaxf(m.w, v23.y);
    }
    float4 p = *(const float4*)(g_p + node * 64 + hl * 4);
    float r0 = fmaxf(p.x + m.x, 0.f);
    float r1 = fmaxf(p.y + m.y, 0.f);
    float r2 = fmaxf(p.z + m.z, 0.f);
    float r3 = fmaxf(p.w + m.w, 0.f);
    __nv_bfloat16 h0 = __float2bfloat16(r0), h1 = __float2bfloat16(r1);
    __nv_bfloat16 h2 = __float2bfloat16(r2), h3 = __float2bfloat16(r3);
    __nv_bfloat16 l0 = __float2bfloat16(r0 - __bfloat162float(h0));
    __nv_bfloat16 l1 = __float2bfloat16(r1 - __bfloat162float(h1));
    __nv_bfloat16 l2 = __float2bfloat16(r2 - __bfloat162float(h2));
    __nv_bfloat16 l3 = __float2bfloat16(r3 - __bfloat162float(h3));
    __nv_bfloat162 hp0 = __halves2bfloat162(h0, h1);
    __nv_bfloat162 hp1 = __halves2bfloat162(h2, h3);
    __nv_bfloat162 lp0 = __halves2bfloat162(l0, l1);
    __nv_bfloat162 lp1 = __halves2bfloat162(l2, l3);
    uint2 hv = make_uint2(*(u32*)&hp0, *(u32*)&hp1);
    uint2 lv = make_uint2(*(u32*)&lp0, *(u32*)&lp1);
    *(uint2*)(g_hhi + node * 64 + hl * 4) = hv;
    *(uint2*)(g_hlo + node * 64 + hl * 4) = lv;
    if (dogmax) {
        if (threadIdx.x < 64) sm[threadIdx.x] = 0u;
        __syncthreads();
        atomicMax(&sm[hl * 4 + 0], __float_as_uint(r0));   // r >= 0
        atomicMax(&sm[hl * 4 + 1], __float_as_uint(r1));
        atomicMax(&sm[hl * 4 + 2], __float_as_uint(r2));
        atomicMax(&sm[hl * 4 + 3], __float_as_uint(r3));
        __syncthreads();
        if (threadIdx.x < 64) atomicMax(&g_gmax[threadIdx.x], sm[threadIdx.x]);
    }
}

// ---------------- mma / ldmatrix / cp.async helpers -------------------------
static __device__ __forceinline__ void mma16816(float d[4], const u32 a[4],
                                                const u32 b[2]) {
    asm volatile(
        "mma.sync.aligned.m16n8k16.row.col.f32.bf16.bf16.f32 "
        "{%0,%1,%2,%3}, {%4,%5,%6,%7}, {%8,%9}, {%0,%1,%2,%3};"
        : "+f"(d[0]), "+f"(d[1]), "+f"(d[2]), "+f"(d[3])
        : "r"(a[0]), "r"(a[1]), "r"(a[2]), "r"(a[3]), "r"(b[0]), "r"(b[1]));
}
static __device__ __forceinline__ void ldsm4(u32 r[4], u32 addr) {
    asm volatile("ldmatrix.sync.aligned.m8n8.x4.shared.b16 {%0,%1,%2,%3}, [%4];"
        : "=r"(r[0]), "=r"(r[1]), "=r"(r[2]), "=r"(r[3]) : "r"(addr));
}
static __device__ __forceinline__ u32 smem_u32(const void* p) {
    u32 a;
    asm("{ .reg .u64 t; cvta.to.shared.u64 t, %1; cvt.u32.u64 %0, t; }"
        : "=r"(a) : "l"(p));
    return a;
}
static __device__ __forceinline__ void cpasync16(u32 dst, const void* src) {
    asm volatile("cp.async.cg.shared.global [%0], [%1], 16;"
        :: "r"(dst), "l"(src) : "memory");
}
static __device__ __forceinline__ void cpasync_wait_all() {
    asm volatile("cp.async.commit_group;\n\tcp.async.wait_group 0;" ::: "memory");
}

// ---------------- tensor-core GEMM: h[N,64] @ Wc[64,128] --------------------
// R14 shape: CTA 128M x 128N, grid 782, 512 thr / 16 warps (warp 16M x 64N),
// __launch_bounds__(512,2). 3-pass bf16 hi/lo split, fp32 accum.
// smem: Bhi[128][72]@0, Blo@18432, Ahi[128][72]@36864, Alo@55296,
//       bias@73728 (512B), Wb@74240 (1536B). Total 75776 B.
// mode 0: warp group wn=0 stores p cols (f32 -> g_p), wn=1 stores q cols
//         (fp16 -> g_q); bias on cols 0-63 only.
// mode 1 (fused head): bias g_c128, relu, out += relu(feat) @ Wb via
//   quad-shfl reduction + atomicAdd (out pre-init to x + bb).
__global__ void __launch_bounds__(512, 2) tc_gemm_kernel(int layer,
                                                         const float* __restrict__ bias,
                                                         int mode,
                                                         const float* __restrict__ Wb,
                                                         float* __restrict__ out) {
    extern __shared__ unsigned char smem[];
    float* sB  = (float*)(smem + 73728);
    float* sWb = (float*)(smem + 74240);
    int tid = threadIdx.x;
    int nb  = blockIdx.x * 128;
    u32 sbase = smem_u32(smem);

    // B: 128 rows x 8 chunks x {hi,lo} = 2048 chunks
    {
        const char* wh = (const char*)(g_whi + layer * 8192);
        const char* wl = (const char*)(g_wlo + layer * 8192);
#pragma unroll
        for (int c = tid; c < 2048; c += 512) {
            int half = c >> 10, idx = c & 1023;
            u32 off = (u32)(idx >> 3) * 144 + (u32)(idx & 7) * 16;
            cpasync16(sbase + half * 18432 + off,
                      (half ? wl : wh) + idx * 16);
        }
    }
    // A: 128 rows x 8 chunks x {hi,lo} = 2048 chunks (gmem oversized past NN)
    {
        const char* ah = (const char*)(g_hhi + (size_t)nb * 64);
        const char* al = (const char*)(g_hlo + (size_t)nb * 64);
#pragma unroll
        for (int c = tid; c < 2048; c += 512) {
            int half = c >> 10, idx = c & 1023;
            u32 off = (u32)(idx >> 3) * 144 + (u32)(idx & 7) * 16;
            cpasync16(sbase + 36864 + half * 18432 + off,
                      (half ? al : ah) + idx * 16);
        }
    }
    if (tid < 128)
        sB[tid] = (mode == 0) ? ((tid < 64) ? bias[tid] : 0.f) : g_c128[tid];
    if (mode == 1 && tid < 384) sWb[tid] = Wb[tid];
    cpasync_wait_all();
    __syncthreads();

    int lane = tid & 31;
    int wid  = tid >> 5;
    int wm   = wid & 7;      // 16-row group: rows wm*16..+16
    int wn   = wid >> 3;     // cols wn*64..+64

    int brow = wn * 64 + (lane & 7) + ((lane >> 4) << 3);
    u32 bHi = sbase + (brow * 72 + ((lane >> 3) & 1) * 8) * 2;
    u32 bLo = bHi + 18432;
    u32 aHi = sbase + 36864 +
              ((wm * 16 + (lane & 15)) * 72 + (lane >> 4) * 8) * 2;
    u32 aLo = aHi + 18432;
    int r = lane >> 2, q = lane & 3;

    float d[8][4];
#pragma unroll
    for (int nf = 0; nf < 8; nf++)
#pragma unroll
        for (int j = 0; j < 4; j++) d[nf][j] = 0.f;

#pragma unroll
    for (int kk = 0; kk < 4; kk++) {
        int ko = kk * 32;
        u32 ah[4], al[4], bb[4][4];
        ldsm4(ah, aHi + ko);
        ldsm4(al, aLo + ko);
#pragma unroll
        for (int p2 = 0; p2 < 4; p2++) ldsm4(bb[p2], bHi + p2 * 2304 + ko);
#pragma unroll
        for (int nf = 0; nf < 8; nf++)
            mma16816(d[nf], ah, &bb[nf >> 1][(nf & 1) * 2]);
#pragma unroll
        for (int nf = 0; nf < 8; nf++)
            mma16816(d[nf], al, &bb[nf >> 1][(nf & 1) * 2]);
#pragma unroll
        for (int p2 = 0; p2 < 4; p2++) ldsm4(bb[p2], bLo + p2 * 2304 + ko);
#pragma unroll
        for (int nf = 0; nf < 8; nf++)
            mma16816(d[nf], ah, &bb[nf >> 1][(nf & 1) * 2]);
    }

    int row0 = nb + wm * 16 + r;
    if (mode == 0) {
#pragma unroll
        for (int nf = 0; nf < 8; nf++) {
            int ccol = wn * 64 + nf * 8 + 2 * q;
            float bx = sB[ccol], by = sB[ccol + 1];
            float2 v0 = make_float2(d[nf][0] + bx, d[nf][1] + by);
            float2 v1 = make_float2(d[nf][2] + bx, d[nf][3] + by);
            if (wn == 0) {
                // p columns -> f32
                if (row0 < NN)     *(float2*)(g_p + row0 * 64 + ccol)       = v0;
                if (row0 + 8 < NN) *(float2*)(g_p + (row0 + 8) * 64 + ccol) = v1;
            } else {
                // q columns -> fp16
                int qc = ccol - 64;
                __half2 q0 = __floats2half2_rn(v0.x, v0.y);
                __half2 q1 = __floats2half2_rn(v1.x, v1.y);
                if (row0 < NN)     *(__half2*)(g_q + row0 * 64 + qc)       = q0;
                if (row0 + 8 < NN) *(__half2*)(g_q + (row0 + 8) * 64 + qc) = q1;
            }
        }
    } else {
        float o0[3] = {0.f, 0.f, 0.f};
        float o1[3] = {0.f, 0.f, 0.f};
#pragma unroll
        for (int nf = 0; nf < 8; nf++) {
            int gcol = wn * 64 + nf * 8 + 2 * q;
            float bx = sB[gcol], by = sB[gcol + 1];
            float v00 = fmaxf(d[nf][0] + bx, 0.f);
            float v01 = fmaxf(d[nf][1] + by, 0.f);
            float v10 = fmaxf(d[nf][2] + bx, 0.f);
            float v11 = fmaxf(d[nf][3] + by, 0.f);
#pragma unroll
            for (int c = 0; c < 3; c++) {
                float wb0 = sWb[gcol * 3 + c];
                float wb1 = sWb[(gcol + 1) * 3 + c];
                o0[c] += v00 * wb0 + v01 * wb1;
                o1[c] += v10 * wb0 + v11 * wb1;
            }
        }
#pragma unroll
        for (int msk = 1; msk <= 2; msk <<= 1) {
#pragma unroll
            for (int c = 0; c < 3; c++) {
                o0[c] += __shfl_xor_sync(0xffffffffu, o0[c], msk);
                o1[c] += __shfl_xor_sync(0xffffffffu, o1[c], msk);
            }
        }
        if (q == 0) {
#pragma unroll
            for (int c = 0; c < 3; c++) {
                if (row0 < NN)     atomicAdd(out + row0 * 3 + c,       o0[c]);
                if (row0 + 8 < NN) atomicAdd(out + (row0 + 8) * 3 + c, o1[c]);
            }
        }
    }
}

// ---------------- c128 (block 0) + out init (blocks 1..) --------------------
__global__ void c128_kernel(const float* __restrict__ Wa,
                            const float* __restrict__ ba,
                            const float* __restrict__ bb,
                            const float* __restrict__ x,
                            float* __restrict__ out) {
    if (blockIdx.x == 0) {
        int t = threadIdx.x;
        if (t < 128) {
            float s = ba[t];
#pragma unroll 8
            for (int c = 0; c < 64; c++)
                s += __uint_as_float(g_gmax[c]) * Wa[(64 + c) * 128 + t];
            g_c128[t] = s;
        }
        return;
    }
    int idx = (blockIdx.x - 1) * 256 + threadIdx.x;
    if (idx < NN * 3) {
        int c = idx - (idx / 3) * 3;
        out[idx] = x[idx] + bb[c];
    }
}

// ---------------- launch ----------------------------------------------------
extern "C" void kernel_launch(void* const* d_in, const int* in_sizes, int n_in,
                              void* d_out, int out_size) {
    (void)in_sizes; (void)n_in; (void)out_size;
    const float* x  = (const float*)d_in[0];
    const int*   ei = (const int*)d_in[1];
    const float* W1 = (const float*)d_in[2];
    const float* b1 = (const float*)d_in[3];
    const float* Wl[4] = {(const float*)d_in[4], (const float*)d_in[6],
                          (const float*)d_in[8], (const float*)d_in[10]};
    const float* bl[4] = {(const float*)d_in[5], (const float*)d_in[7],
                          (const float*)d_in[9], (const float*)d_in[11]};
    const float* Wa = (const float*)d_in[12];
    const float* ba = (const float*)d_in[13];
    const float* Wb = (const float*)d_in[14];
    const float* bb = (const float*)d_in[15];
    float* out = (float*)d_out;

    const int GEMM_SMEM = 75776;
    static bool attr_set = false;
    if (!attr_set) {
        cudaFuncSetAttribute(tc_gemm_kernel,
                             cudaFuncAttributeMaxDynamicSharedMemorySize,
                             GEMM_SMEM);
        attr_set = true;
    }

    convert_kernel<<<(EE + 255) / 256, 256>>>(ei);                        // #1
    layer1_kernel<<<12505, 256>>>(x, W1, b1, Wl[0], Wl[1], Wl[2], Wl[3], Wa); // #2
    edge_kernel<<<(NN * 16) / 256, 256>>>(0);                             // #3

    for (int l = 0; l < 4; l++) {
        tc_gemm_kernel<<<NT128, 512, GEMM_SMEM>>>(l, bl[l], 0, nullptr, nullptr);
        edge_kernel<<<(NN * 16) / 256, 256>>>(l == 3 ? 1 : 0);
    }

    // c128 + out = x + bb init (must precede fused GEMM-5)
    c128_kernel<<<1 + (NN * 3 + 255) / 256, 256>>>(Wa, ba, bb, x, out);
    // GEMM-5 with fused head: out += relu(h@Wa[0:64] + c128) @ Wb
    tc_gemm_kernel<<<NT128, 512, GEMM_SMEM>>>(4, nullptr, 1, Wb, out);
}

// round 16
// speedup vs baseline: 1.6735x; 1.1851x over previous
#include <cuda_runtime.h>
#include <cuda_bf16.h>
#include <cuda_fp16.h>
#include <cstdint>

#define NN 100000
#define EE 1600000
#define NT128 ((NN + 127) / 128)   // 782 tiles of 128 rows

typedef uint32_t u32;

// ---------------- scratch (static device globals; no allocations) ----------
__device__ __half         g_h16[(NN + 128) * 64];  // node features (fp16)
__device__ float          g_p[(NN + 128) * 64];    // p (f32)
__device__ __half         g_q[(NN + 128) * 64];    // q (fp16)
__device__ int            g_src[EE];       // int32 source indices
__device__ unsigned       g_gmax[64];      // global max bits (values >= 0)
__device__ float          g_c128[128];     // head constant: g @ Wa[64:128] + ba
__device__ __half         g_w16[5 * 128 * 64];  // fp16 weights, [n][k] flat

// ---------------- convert (fused gmax zero + dtype detect) ------------------
__global__ void convert_kernel(const int* __restrict__ ei) {
    __shared__ int s64;
    if (blockIdx.x == 0 && threadIdx.x < 64) g_gmax[threadIdx.x] = 0u;
    if (threadIdx.x == 0) {
        // int64 layout => odd words of src row all zero (0<=src<1e5);
        // int32 layout => P(all 64 zero) ~ 1e-320.
        int z = 0;
        for (int i = 0; i < 64; i++) z += (ei[2 * i + 1] == 0) ? 1 : 0;
        s64 = (z == 64) ? 1 : 0;
    }
    __syncthreads();
    int e = blockIdx.x * blockDim.x + threadIdx.x;
    if (e < EE) g_src[e] = s64 ? ei[2 * e] : ei[e];
}

// ---------------- layer 1: warp-per-node + fused weight prep ---------------
__global__ void layer1_kernel(const float* __restrict__ x,
                              const float* __restrict__ W1,
                              const float* __restrict__ b1,
                              const float* __restrict__ Wl0,
                              const float* __restrict__ Wl1,
                              const float* __restrict__ Wl2,
                              const float* __restrict__ Wl3,
                              const float* __restrict__ Wa) {
    if (blockIdx.x >= 12500) {
        int b = blockIdx.x - 12500;
        const float* W = (b == 0) ? Wl0 : (b == 1) ? Wl1 : (b == 2) ? Wl2
                       : (b == 3) ? Wl3 : Wa;
        for (int i = threadIdx.x; i < 8192; i += 256) {
            int n = i >> 6, k = i & 63;
            float wv;
            if (b < 4)
                wv = (n < 64) ? (W[k * 64 + n] - W[(k + 64) * 64 + n])
                              : W[(k + 64) * 64 + (n - 64)];
            else
                wv = W[k * 128 + n];
            g_w16[b * 8192 + i] = __float2half(wv);
        }
        return;
    }
    __shared__ float sW[384];   // W1: 6 rows x 64
    __shared__ float sb[64];
    int tid = threadIdx.x;
    for (int i = tid; i < 448; i += 256) {
        if (i < 384) sW[i] = W1[i];
        else         sb[i - 384] = b1[i - 384];
    }
    __syncthreads();
    int lane = tid & 31;
    int node = blockIdx.x * 8 + (tid >> 5);
    float xv = (lane < 3) ? x[node * 3 + lane] : 0.f;
    float x0 = __shfl_sync(0xffffffffu, xv, 0);
    float x1 = __shfl_sync(0xffffffffu, xv, 1);
    float x2 = __shfl_sync(0xffffffffu, xv, 2);
    int c = lane * 2;
    float w30 = sW[192 + c], w31 = sW[193 + c];
    float w40 = sW[256 + c], w41 = sW[257 + c];
    float w50 = sW[320 + c], w51 = sW[321 + c];
    float q0 = x0 * w30 + x1 * w40 + x2 * w50;
    float q1 = x0 * w31 + x1 * w41 + x2 * w51;
    float p0 = sb[c]     + x0 * (sW[c] - w30)     + x1 * (sW[64 + c] - w40)
                         + x2 * (sW[128 + c] - w50);
    float p1 = sb[c + 1] + x0 * (sW[c + 1] - w31) + x1 * (sW[65 + c] - w41)
                         + x2 * (sW[129 + c] - w51);
    *(float2*)(g_p + node * 64 + c) = make_float2(p0, p1);
    __half2 qh = __floats2half2_rn(q0, q1);
    *(__half2*)(g_q + node * 64 + c) = qh;
}

// ---------------- edge max: 2 nodes per warp, fp16 q gather, fp16 h out -----
__global__ void edge_kernel(int dogmax) {
    __shared__ unsigned sm[64];
    int gw   = (blockIdx.x * blockDim.x + threadIdx.x) >> 5;  // warp: 2 nodes
    int lane = threadIdx.x & 31;
    int half = lane >> 4;
    int hl   = lane & 15;
    int node = gw * 2 + half;
    int s = g_src[gw * 32 + lane];   // lanes 0-15: node0 srcs, 16-31: node1
    float4 m = make_float4(-3.402823466e38f, -3.402823466e38f,
                           -3.402823466e38f, -3.402823466e38f);
#pragma unroll
    for (int k = 0; k < 16; k++) {
        int j = __shfl_sync(0xffffffffu, s, (half << 4) + k);
        uint2 qv = *(const uint2*)(g_q + j * 64 + hl * 4);   // 4 halves
        float2 v01 = __half22float2(*(__half2*)&qv.x);
        float2 v23 = __half22float2(*(__half2*)&qv.y);
        m.x = fmaxf(m.x, v01.x);
        m.y = fmaxf(m.y, v01.y);
        m.z = fmaxf(m.z, v23.x);
        m.w = fmaxf(m.w, v23.y);
    }
    float4 p = *(const float4*)(g_p + node * 64 + hl * 4);
    float r0 = fmaxf(p.x + m.x, 0.f);
    float r1 = fmaxf(p.y + m.y, 0.f);
    float r2 = fmaxf(p.z + m.z, 0.f);
    float r3 = fmaxf(p.w + m.w, 0.f);
    __half2 h01 = __floats2half2_rn(r0, r1);
    __half2 h23 = __floats2half2_rn(r2, r3);
    *(uint2*)(g_h16 + node * 64 + hl * 4) = make_uint2(*(u32*)&h01, *(u32*)&h23);
    if (dogmax) {
        if (threadIdx.x < 64) sm[threadIdx.x] = 0u;
        __syncthreads();
        atomicMax(&sm[hl * 4 + 0], __float_as_uint(r0));   // r >= 0
        atomicMax(&sm[hl * 4 + 1], __float_as_uint(r1));
        atomicMax(&sm[hl * 4 + 2], __float_as_uint(r2));
        atomicMax(&sm[hl * 4 + 3], __float_as_uint(r3));
        __syncthreads();
        if (threadIdx.x < 64) atomicMax(&g_gmax[threadIdx.x], sm[threadIdx.x]);
    }
}

// ---------------- mma / ldmatrix / cp.async helpers -------------------------
static __device__ __forceinline__ void mma16816f16(float d[4], const u32 a[4],
                                                   const u32 b[2]) {
    asm volatile(
        "mma.sync.aligned.m16n8k16.row.col.f32.f16.f16.f32 "
        "{%0,%1,%2,%3}, {%4,%5,%6,%7}, {%8,%9}, {%0,%1,%2,%3};"
        : "+f"(d[0]), "+f"(d[1]), "+f"(d[2]), "+f"(d[3])
        : "r"(a[0]), "r"(a[1]), "r"(a[2]), "r"(a[3]), "r"(b[0]), "r"(b[1]));
}
static __device__ __forceinline__ void ldsm4(u32 r[4], u32 addr) {
    asm volatile("ldmatrix.sync.aligned.m8n8.x4.shared.b16 {%0,%1,%2,%3}, [%4];"
        : "=r"(r[0]), "=r"(r[1]), "=r"(r[2]), "=r"(r[3]) : "r"(addr));
}
static __device__ __forceinline__ u32 smem_u32(const void* p) {
    u32 a;
    asm("{ .reg .u64 t; cvta.to.shared.u64 t, %1; cvt.u32.u64 %0, t; }"
        : "=r"(a) : "l"(p));
    return a;
}
static __device__ __forceinline__ void cpasync16(u32 dst, const void* src) {
    asm volatile("cp.async.cg.shared.global [%0], [%1], 16;"
        :: "r"(dst), "l"(src) : "memory");
}
static __device__ __forceinline__ void cpasync_wait_all() {
    asm volatile("cp.async.commit_group;\n\tcp.async.wait_group 0;" ::: "memory");
}

// ---------------- tensor-core GEMM: h[N,64] @ Wc[64,128] (single-pass fp16) -
// CTA 128M x 128N, grid 782, 512 thr / 16 warps (warp 16M x 64N),
// __launch_bounds__(512,2). SINGLE-PASS fp16 mma (no hi/lo split): 32 mma +
// 20 ldsm per warp (was 96/48). fp32 accum.
// smem: B[128][72] halves @0 (18432B), A[128][72] @18432 (18432B),
//       bias f32[128] @36864 (512B), Wb @37376 (1536B). Total 38912 B.
// mode 0: wn=0 stores p (f32 -> g_p), wn=1 stores q (fp16 -> g_q);
//         bias applies to cols 0-63 only.
// mode 1 (fused head): bias g_c128, relu, out += relu(feat) @ Wb via
//   quad-shfl reduction + atomicAdd (out pre-init to x + bb).
__global__ void __launch_bounds__(512, 2) tc_gemm_kernel(int layer,
                                                         const float* __restrict__ bias,
                                                         int mode,
                                                         const float* __restrict__ Wb,
                                                         float* __restrict__ out) {
    extern __shared__ unsigned char smem[];
    float* sB  = (float*)(smem + 36864);
    float* sWb = (float*)(smem + 37376);
    int tid = threadIdx.x;
    int nb  = blockIdx.x * 128;
    u32 sbase = smem_u32(smem);

    // B: 128 rows x 8 chunks = 1024 chunks
    {
        const char* wsrc = (const char*)(g_w16 + layer * 8192);
#pragma unroll
        for (int c = tid; c < 1024; c += 512) {
            u32 off = (u32)(c >> 3) * 144 + (u32)(c & 7) * 16;
            cpasync16(sbase + off, wsrc + c * 16);
        }
    }
    // A: 128 rows x 8 chunks = 1024 chunks (gmem oversized past NN)
    {
        const char* asrc = (const char*)(g_h16 + (size_t)nb * 64);
#pragma unroll
        for (int c = tid; c < 1024; c += 512) {
            u32 off = (u32)(c >> 3) * 144 + (u32)(c & 7) * 16;
            cpasync16(sbase + 18432 + off, asrc + c * 16);
        }
    }
    if (tid < 128)
        sB[tid] = (mode == 0) ? ((tid < 64) ? bias[tid] : 0.f) : g_c128[tid];
    if (mode == 1 && tid < 384) sWb[tid] = Wb[tid];
    cpasync_wait_all();
    __syncthreads();

    int lane = tid & 31;
    int wid  = tid >> 5;
    int wm   = wid & 7;      // 16-row group: rows wm*16..+16
    int wn   = wid >> 3;     // cols wn*64..+64

    int brow = wn * 64 + (lane & 7) + ((lane >> 4) << 3);
    u32 bA = sbase + (brow * 72 + ((lane >> 3) & 1) * 8) * 2;
    u32 aA = sbase + 18432 +
             ((wm * 16 + (lane & 15)) * 72 + (lane >> 4) * 8) * 2;
    int r = lane >> 2, q = lane & 3;

    float d[8][4];
#pragma unroll
    for (int nf = 0; nf < 8; nf++)
#pragma unroll
        for (int j = 0; j < 4; j++) d[nf][j] = 0.f;

#pragma unroll
    for (int kk = 0; kk < 4; kk++) {
        int ko = kk * 32;
        u32 a[4], bb[4][4];
        ldsm4(a, aA + ko);
#pragma unroll
        for (int p2 = 0; p2 < 4; p2++) ldsm4(bb[p2], bA + p2 * 2304 + ko);
#pragma unroll
        for (int nf = 0; nf < 8; nf++)
            mma16816f16(d[nf], a, &bb[nf >> 1][(nf & 1) * 2]);
    }

    int row0 = nb + wm * 16 + r;
    if (mode == 0) {
#pragma unroll
        for (int nf = 0; nf < 8; nf++) {
            int ccol = wn * 64 + nf * 8 + 2 * q;
            float bx = sB[ccol], by = sB[ccol + 1];
            float2 v0 = make_float2(d[nf][0] + bx, d[nf][1] + by);
            float2 v1 = make_float2(d[nf][2] + bx, d[nf][3] + by);
            if (wn == 0) {
                // p columns -> f32
                if (row0 < NN)     *(float2*)(g_p + row0 * 64 + ccol)       = v0;
                if (row0 + 8 < NN) *(float2*)(g_p + (row0 + 8) * 64 + ccol) = v1;
            } else {
                // q columns -> fp16
                int qc = ccol - 64;
                __half2 q0 = __floats2half2_rn(v0.x, v0.y);
                __half2 q1 = __floats2half2_rn(v1.x, v1.y);
                if (row0 < NN)     *(__half2*)(g_q + row0 * 64 + qc)       = q0;
                if (row0 + 8 < NN) *(__half2*)(g_q + (row0 + 8) * 64 + qc) = q1;
            }
        }
    } else {
        float o0[3] = {0.f, 0.f, 0.f};
        float o1[3] = {0.f, 0.f, 0.f};
#pragma unroll
        for (int nf = 0; nf < 8; nf++) {
            int gcol = wn * 64 + nf * 8 + 2 * q;
            float bx = sB[gcol], by = sB[gcol + 1];
            float v00 = fmaxf(d[nf][0] + bx, 0.f);
            float v01 = fmaxf(d[nf][1] + by, 0.f);
            float v10 = fmaxf(d[nf][2] + bx, 0.f);
            float v11 = fmaxf(d[nf][3] + by, 0.f);
#pragma unroll
            for (int c = 0; c < 3; c++) {
                float wb0 = sWb[gcol * 3 + c];
                float wb1 = sWb[(gcol + 1) * 3 + c];
                o0[c] += v00 * wb0 + v01 * wb1;
                o1[c] += v10 * wb0 + v11 * wb1;
            }
        }
#pragma unroll
        for (int msk = 1; msk <= 2; msk <<= 1) {
#pragma unroll
            for (int c = 0; c < 3; c++) {
                o0[c] += __shfl_xor_sync(0xffffffffu, o0[c], msk);
                o1[c] += __shfl_xor_sync(0xffffffffu, o1[c], msk);
            }
        }
        if (q == 0) {
#pragma unroll
            for (int c = 0; c < 3; c++) {
                if (row0 < NN)     atomicAdd(out + row0 * 3 + c,       o0[c]);
                if (row0 + 8 < NN) atomicAdd(out + (row0 + 8) * 3 + c, o1[c]);
            }
        }
    }
}

// ---------------- c128 (block 0) + out init (blocks 1..) --------------------
__global__ void c128_kernel(const float* __restrict__ Wa,
                            const float* __restrict__ ba,
                            const float* __restrict__ bb,
                            const float* __restrict__ x,
                            float* __restrict__ out) {
    if (blockIdx.x == 0) {
        int t = threadIdx.x;
        if (t < 128) {
            float s = ba[t];
#pragma unroll 8
            for (int c = 0; c < 64; c++)
                s += __uint_as_float(g_gmax[c]) * Wa[(64 + c) * 128 + t];
            g_c128[t] = s;
        }
        return;
    }
    int idx = (blockIdx.x - 1) * 256 + threadIdx.x;
    if (idx < NN * 3) {
        int c = idx - (idx / 3) * 3;
        out[idx] = x[idx] + bb[c];
    }
}

// ---------------- launch ----------------------------------------------------
extern "C" void kernel_launch(void* const* d_in, const int* in_sizes, int n_in,
                              void* d_out, int out_size) {
    (void)in_sizes; (void)n_in; (void)out_size;
    const float* x  = (const float*)d_in[0];
    const int*   ei = (const int*)d_in[1];
    const float* W1 = (const float*)d_in[2];
    const float* b1 = (const float*)d_in[3];
    const float* Wl[4] = {(const float*)d_in[4], (const float*)d_in[6],
                          (const float*)d_in[8], (const float*)d_in[10]};
    const float* bl[4] = {(const float*)d_in[5], (const float*)d_in[7],
                          (const float*)d_in[9], (const float*)d_in[11]};
    const float* Wa = (const float*)d_in[12];
    const float* ba = (const float*)d_in[13];
    const float* Wb = (const float*)d_in[14];
    const float* bb = (const float*)d_in[15];
    float* out = (float*)d_out;

    const int GEMM_SMEM = 38912;
    static bool attr_set = false;
    if (!attr_set) {
        cudaFuncSetAttribute(tc_gemm_kernel,
                             cudaFuncAttributeMaxDynamicSharedMemorySize,
                             GEMM_SMEM);
        attr_set = true;
    }

    convert_kernel<<<(EE + 255) / 256, 256>>>(ei);                        // #1
    layer1_kernel<<<12505, 256>>>(x, W1, b1, Wl[0], Wl[1], Wl[2], Wl[3], Wa); // #2
    edge_kernel<<<(NN * 16) / 256, 256>>>(0);                             // #3

    for (int l = 0; l < 4; l++) {
        tc_gemm_kernel<<<NT128, 512, GEMM_SMEM>>>(l, bl[l], 0, nullptr, nullptr);
        edge_kernel<<<(NN * 16) / 256, 256>>>(l == 3 ? 1 : 0);
    }

    // c128 + out = x + bb init (must precede fused GEMM-5)
    c128_kernel<<<1 + (NN * 3 + 255) / 256, 256>>>(Wa, ba, bb, x, out);
    // GEMM-5 with fused head: out += relu(h@Wa[0:64] + c128) @ Wb
    tc_gemm_kernel<<<NT128, 512, GEMM_SMEM>>>(4, nullptr, 1, Wb, out);
}

// round 17
// speedup vs baseline: 1.6848x; 1.0067x over previous
#include <cuda_runtime.h>
#include <cuda_bf16.h>
#include <cuda_fp16.h>
#include <cstdint>

#define NN 100000
#define EE 1600000
#define NT128 ((NN + 127) / 128)   // 782 tiles of 128 rows

typedef uint32_t u32;

// ---------------- scratch (static device globals; no allocations) ----------
__device__ __half         g_h16[(NN + 128) * 64];  // node features (fp16)
__device__ __half         g_p[(NN + 128) * 64];    // p (fp16)
__device__ __half         g_q[(NN + 128) * 64];    // q (fp16)
__device__ int            g_src[EE];       // int32 source indices
__device__ unsigned       g_gmax[64];      // global max bits (values >= 0)
__device__ float          g_c128[128];     // head constant: g @ Wa[64:128] + ba
__device__ __half         g_w16[5 * 128 * 64];  // fp16 weights, [n][k] flat

// ---------------- convert (fused gmax zero + dtype detect) ------------------
__global__ void convert_kernel(const int* __restrict__ ei) {
    __shared__ int s64;
    if (blockIdx.x == 0 && threadIdx.x < 64) g_gmax[threadIdx.x] = 0u;
    if (threadIdx.x == 0) {
        // int64 layout => odd words of src row all zero (0<=src<1e5);
        // int32 layout => P(all 64 zero) ~ 1e-320.
        int z = 0;
        for (int i = 0; i < 64; i++) z += (ei[2 * i + 1] == 0) ? 1 : 0;
        s64 = (z == 64) ? 1 : 0;
    }
    __syncthreads();
    int e = blockIdx.x * blockDim.x + threadIdx.x;
    if (e < EE) g_src[e] = s64 ? ei[2 * e] : ei[e];
}

// ---------------- layer 1: warp-per-node + fused weight prep ---------------
__global__ void layer1_kernel(const float* __restrict__ x,
                              const float* __restrict__ W1,
                              const float* __restrict__ b1,
                              const float* __restrict__ Wl0,
                              const float* __restrict__ Wl1,
                              const float* __restrict__ Wl2,
                              const float* __restrict__ Wl3,
                              const float* __restrict__ Wa) {
    if (blockIdx.x >= 12500) {
        int b = blockIdx.x - 12500;
        const float* W = (b == 0) ? Wl0 : (b == 1) ? Wl1 : (b == 2) ? Wl2
                       : (b == 3) ? Wl3 : Wa;
        for (int i = threadIdx.x; i < 8192; i += 256) {
            int n = i >> 6, k = i & 63;
            float wv;
            if (b < 4)
                wv = (n < 64) ? (W[k * 64 + n] - W[(k + 64) * 64 + n])
                              : W[(k + 64) * 64 + (n - 64)];
            else
                wv = W[k * 128 + n];
            g_w16[b * 8192 + i] = __float2half(wv);
        }
        return;
    }
    __shared__ float sW[384];   // W1: 6 rows x 64
    __shared__ float sb[64];
    int tid = threadIdx.x;
    for (int i = tid; i < 448; i += 256) {
        if (i < 384) sW[i] = W1[i];
        else         sb[i - 384] = b1[i - 384];
    }
    __syncthreads();
    int lane = tid & 31;
    int node = blockIdx.x * 8 + (tid >> 5);
    float xv = (lane < 3) ? x[node * 3 + lane] : 0.f;
    float x0 = __shfl_sync(0xffffffffu, xv, 0);
    float x1 = __shfl_sync(0xffffffffu, xv, 1);
    float x2 = __shfl_sync(0xffffffffu, xv, 2);
    int c = lane * 2;
    float w30 = sW[192 + c], w31 = sW[193 + c];
    float w40 = sW[256 + c], w41 = sW[257 + c];
    float w50 = sW[320 + c], w51 = sW[321 + c];
    float q0 = x0 * w30 + x1 * w40 + x2 * w50;
    float q1 = x0 * w31 + x1 * w41 + x2 * w51;
    float p0 = sb[c]     + x0 * (sW[c] - w30)     + x1 * (sW[64 + c] - w40)
                         + x2 * (sW[128 + c] - w50);
    float p1 = sb[c + 1] + x0 * (sW[c + 1] - w31) + x1 * (sW[65 + c] - w41)
                         + x2 * (sW[129 + c] - w51);
    *(__half2*)(g_p + node * 64 + c) = __floats2half2_rn(p0, p1);
    *(__half2*)(g_q + node * 64 + c) = __floats2half2_rn(q0, q1);
}

// ---------------- edge max: 2 nodes per warp, fp16 p/q, fp16 h out ----------
__global__ void edge_kernel(int dogmax) {
    __shared__ unsigned sm[64];
    int gw   = (blockIdx.x * blockDim.x + threadIdx.x) >> 5;  // warp: 2 nodes
    int lane = threadIdx.x & 31;
    int half = lane >> 4;
    int hl   = lane & 15;
    int node = gw * 2 + half;
    int s = g_src[gw * 32 + lane];   // lanes 0-15: node0 srcs, 16-31: node1
    float4 m = make_float4(-3.402823466e38f, -3.402823466e38f,
                           -3.402823466e38f, -3.402823466e38f);
#pragma unroll
    for (int k = 0; k < 16; k++) {
        int j = __shfl_sync(0xffffffffu, s, (half << 4) + k);
        uint2 qv = *(const uint2*)(g_q + j * 64 + hl * 4);   // 4 halves
        float2 v01 = __half22float2(*(__half2*)&qv.x);
        float2 v23 = __half22float2(*(__half2*)&qv.y);
        m.x = fmaxf(m.x, v01.x);
        m.y = fmaxf(m.y, v01.y);
        m.z = fmaxf(m.z, v23.x);
        m.w = fmaxf(m.w, v23.y);
    }
    uint2 pv = *(const uint2*)(g_p + node * 64 + hl * 4);
    float2 p01 = __half22float2(*(__half2*)&pv.x);
    float2 p23 = __half22float2(*(__half2*)&pv.y);
    float r0 = fmaxf(p01.x + m.x, 0.f);
    float r1 = fmaxf(p01.y + m.y, 0.f);
    float r2 = fmaxf(p23.x + m.z, 0.f);
    float r3 = fmaxf(p23.y + m.w, 0.f);
    __half2 h01 = __floats2half2_rn(r0, r1);
    __half2 h23 = __floats2half2_rn(r2, r3);
    *(uint2*)(g_h16 + node * 64 + hl * 4) = make_uint2(*(u32*)&h01, *(u32*)&h23);
    if (dogmax) {
        if (threadIdx.x < 64) sm[threadIdx.x] = 0u;
        __syncthreads();
        atomicMax(&sm[hl * 4 + 0], __float_as_uint(r0));   // r >= 0
        atomicMax(&sm[hl * 4 + 1], __float_as_uint(r1));
        atomicMax(&sm[hl * 4 + 2], __float_as_uint(r2));
        atomicMax(&sm[hl * 4 + 3], __float_as_uint(r3));
        __syncthreads();
        if (threadIdx.x < 64) atomicMax(&g_gmax[threadIdx.x], sm[threadIdx.x]);
    }
}

// ---------------- mma / ldmatrix / cp.async helpers -------------------------
static __device__ __forceinline__ void mma16816f16(float d[4], const u32 a[4],
                                                   const u32 b[2]) {
    asm volatile(
        "mma.sync.aligned.m16n8k16.row.col.f32.f16.f16.f32 "
        "{%0,%1,%2,%3}, {%4,%5,%6,%7}, {%8,%9}, {%0,%1,%2,%3};"
        : "+f"(d[0]), "+f"(d[1]), "+f"(d[2]), "+f"(d[3])
        : "r"(a[0]), "r"(a[1]), "r"(a[2]), "r"(a[3]), "r"(b[0]), "r"(b[1]));
}
static __device__ __forceinline__ void ldsm4(u32 r[4], u32 addr) {
    asm volatile("ldmatrix.sync.aligned.m8n8.x4.shared.b16 {%0,%1,%2,%3}, [%4];"
        : "=r"(r[0]), "=r"(r[1]), "=r"(r[2]), "=r"(r[3]) : "r"(addr));
}
static __device__ __forceinline__ u32 smem_u32(const void* p) {
    u32 a;
    asm("{ .reg .u64 t; cvta.to.shared.u64 t, %1; cvt.u32.u64 %0, t; }"
        : "=r"(a) : "l"(p));
    return a;
}
static __device__ __forceinline__ void cpasync16(u32 dst, const void* src) {
    asm volatile("cp.async.cg.shared.global [%0], [%1], 16;"
        :: "r"(dst), "l"(src) : "memory");
}
static __device__ __forceinline__ void cpasync_wait_all() {
    asm volatile("cp.async.commit_group;\n\tcp.async.wait_group 0;" ::: "memory");
}

// ---------------- tensor-core GEMM: h[N,64] @ Wc[64,128] (single-pass fp16) -
// CTA 128M x 128N, grid 782, 512 thr / 16 warps (warp 16M x 64N),
// __launch_bounds__(512,2). Single-pass fp16 mma, fp32 accum.
// smem: B[128][72] halves @0 (18432B), A[128][72] @18432 (18432B),
//       bias f32[128] @36864 (512B), Wb @37376 (1536B). Total 38912 B.
// mode 0: wn=0 stores p (fp16 -> g_p), wn=1 stores q (fp16 -> g_q);
//         bias applies to cols 0-63 only.
// mode 1 (fused head): bias g_c128, relu, out += relu(feat) @ Wb via
//   quad-shfl reduction + atomicAdd (out pre-init to x + bb).
__global__ void __launch_bounds__(512, 2) tc_gemm_kernel(int layer,
                                                         const float* __restrict__ bias,
                                                         int mode,
                                                         const float* __restrict__ Wb,
                                                         float* __restrict__ out) {
    extern __shared__ unsigned char smem[];
    float* sB  = (float*)(smem + 36864);
    float* sWb = (float*)(smem + 37376);
    int tid = threadIdx.x;
    int nb  = blockIdx.x * 128;
    u32 sbase = smem_u32(smem);

    // B: 128 rows x 8 chunks = 1024 chunks
    {
        const char* wsrc = (const char*)(g_w16 + layer * 8192);
#pragma unroll
        for (int c = tid; c < 1024; c += 512) {
            u32 off = (u32)(c >> 3) * 144 + (u32)(c & 7) * 16;
            cpasync16(sbase + off, wsrc + c * 16);
        }
    }
    // A: 128 rows x 8 chunks = 1024 chunks (gmem oversized past NN)
    {
        const char* asrc = (const char*)(g_h16 + (size_t)nb * 64);
#pragma unroll
        for (int c = tid; c < 1024; c += 512) {
            u32 off = (u32)(c >> 3) * 144 + (u32)(c & 7) * 16;
            cpasync16(sbase + 18432 + off, asrc + c * 16);
        }
    }
    if (tid < 128)
        sB[tid] = (mode == 0) ? ((tid < 64) ? bias[tid] : 0.f) : g_c128[tid];
    if (mode == 1 && tid < 384) sWb[tid] = Wb[tid];
    cpasync_wait_all();
    __syncthreads();

    int lane = tid & 31;
    int wid  = tid >> 5;
    int wm   = wid & 7;      // 16-row group: rows wm*16..+16
    int wn   = wid >> 3;     // cols wn*64..+64

    int brow = wn * 64 + (lane & 7) + ((lane >> 4) << 3);
    u32 bA = sbase + (brow * 72 + ((lane >> 3) & 1) * 8) * 2;
    u32 aA = sbase + 18432 +
             ((wm * 16 + (lane & 15)) * 72 + (lane >> 4) * 8) * 2;
    int r = lane >> 2, q = lane & 3;

    float d[8][4];
#pragma unroll
    for (int nf = 0; nf < 8; nf++)
#pragma unroll
        for (int j = 0; j < 4; j++) d[nf][j] = 0.f;

#pragma unroll
    for (int kk = 0; kk < 4; kk++) {
        int ko = kk * 32;
        u32 a[4], bb[4][4];
        ldsm4(a, aA + ko);
#pragma unroll
        for (int p2 = 0; p2 < 4; p2++) ldsm4(bb[p2], bA + p2 * 2304 + ko);
#pragma unroll
        for (int nf = 0; nf < 8; nf++)
            mma16816f16(d[nf], a, &bb[nf >> 1][(nf & 1) * 2]);
    }

    int row0 = nb + wm * 16 + r;
    if (mode == 0) {
#pragma unroll
        for (int nf = 0; nf < 8; nf++) {
            int ccol = wn * 64 + nf * 8 + 2 * q;
            float bx = sB[ccol], by = sB[ccol + 1];
            float2 v0 = make_float2(d[nf][0] + bx, d[nf][1] + by);
            float2 v1 = make_float2(d[nf][2] + bx, d[nf][3] + by);
            __half2 x0 = __floats2half2_rn(v0.x, v0.y);
            __half2 x1 = __floats2half2_rn(v1.x, v1.y);
            if (wn == 0) {
                // p columns -> fp16
                if (row0 < NN)     *(__half2*)(g_p + row0 * 64 + ccol)       = x0;
                if (row0 + 8 < NN) *(__half2*)(g_p + (row0 + 8) * 64 + ccol) = x1;
            } else {
                // q columns -> fp16
                int qc = ccol - 64;
                if (row0 < NN)     *(__half2*)(g_q + row0 * 64 + qc)       = x0;
                if (row0 + 8 < NN) *(__half2*)(g_q + (row0 + 8) * 64 + qc) = x1;
            }
        }
    } else {
        float o0[3] = {0.f, 0.f, 0.f};
        float o1[3] = {0.f, 0.f, 0.f};
#pragma unroll
        for (int nf = 0; nf < 8; nf++) {
            int gcol = wn * 64 + nf * 8 + 2 * q;
            float bx = sB[gcol], by = sB[gcol + 1];
            float v00 = fmaxf(d[nf][0] + bx, 0.f);
            float v01 = fmaxf(d[nf][1] + by, 0.f);
            float v10 = fmaxf(d[nf][2] + bx, 0.f);
            float v11 = fmaxf(d[nf][3] + by, 0.f);
#pragma unroll
            for (int c = 0; c < 3; c++) {
                float wb0 = sWb[gcol * 3 + c];
                float wb1 = sWb[(gcol + 1) * 3 + c];
                o0[c] += v00 * wb0 + v01 * wb1;
                o1[c] += v10 * wb0 + v11 * wb1;
            }
        }
#pragma unroll
        for (int msk = 1; msk <= 2; msk <<= 1) {
#pragma unroll
            for (int c = 0; c < 3; c++) {
                o0[c] += __shfl_xor_sync(0xffffffffu, o0[c], msk);
                o1[c] += __shfl_xor_sync(0xffffffffu, o1[c], msk);
            }
        }
        if (q == 0) {
#pragma unroll
            for (int c = 0; c < 3; c++) {
                if (row0 < NN)     atomicAdd(out + row0 * 3 + c,       o0[c]);
                if (row0 + 8 < NN) atomicAdd(out + (row0 + 8) * 3 + c, o1[c]);
            }
        }
    }
}

// ---------------- c128 (block 0) + out init (blocks 1..) --------------------
__global__ void c128_kernel(const float* __restrict__ Wa,
                            const float* __restrict__ ba,
                            const float* __restrict__ bb,
                            const float* __restrict__ x,
                            float* __restrict__ out) {
    if (blockIdx.x == 0) {
        int t = threadIdx.x;
        if (t < 128) {
            float s = ba[t];
#pragma unroll 8
            for (int c = 0; c < 64; c++)
                s += __uint_as_float(g_gmax[c]) * Wa[(64 + c) * 128 + t];
            g_c128[t] = s;
        }
        return;
    }
    int idx = (blockIdx.x - 1) * 256 + threadIdx.x;
    if (idx < NN * 3) {
        int c = idx - (idx / 3) * 3;
        out[idx] = x[idx] + bb[c];
    }
}

// ---------------- launch ----------------------------------------------------
extern "C" void kernel_launch(void* const* d_in, const int* in_sizes, int n_in,
                              void* d_out, int out_size) {
    (void)in_sizes; (void)n_in; (void)out_size;
    const float* x  = (const float*)d_in[0];
    const int*   ei = (const int*)d_in[1];
    const float* W1 = (const float*)d_in[2];
    const float* b1 = (const float*)d_in[3];
    const float* Wl[4] = {(const float*)d_in[4], (const float*)d_in[6],
                          (const float*)d_in[8], (const float*)d_in[10]};
    const float* bl[4] = {(const float*)d_in[5], (const float*)d_in[7],
                          (const float*)d_in[9], (const float*)d_in[11]};
    const float* Wa = (const float*)d_in[12];
    const float* ba = (const float*)d_in[13];
    const float* Wb = (const float*)d_in[14];
    const float* bb = (const float*)d_in[15];
    float* out = (float*)d_out;

    const int GEMM_SMEM = 38912;
    static bool attr_set = false;
    if (!attr_set) {
        cudaFuncSetAttribute(tc_gemm_kernel,
                             cudaFuncAttributeMaxDynamicSharedMemorySize,
                             GEMM_SMEM);
        attr_set = true;
    }

    convert_kernel<<<(EE + 255) / 256, 256>>>(ei);                        // #1
    layer1_kernel<<<12505, 256>>>(x, W1, b1, Wl[0], Wl[1], Wl[2], Wl[3], Wa); // #2
    edge_kernel<<<(NN * 16) / 256, 256>>>(0);                             // #3

    for (int l = 0; l < 4; l++) {
        tc_gemm_kernel<<<NT128, 512, GEMM_SMEM>>>(l, bl[l], 0, nullptr, nullptr);
        edge_kernel<<<(NN * 16) / 256, 256>>>(l == 3 ? 1 : 0);
    }

    // c128 + out = x + bb init (must precede fused GEMM-5)
    c128_kernel<<<1 + (NN * 3 + 255) / 256, 256>>>(Wa, ba, bb, x, out);
    // GEMM-5 with fused head: out += relu(h@Wa[0:64] + c128) @ Wb
    tc_gemm_kernel<<<NT128, 512, GEMM_SMEM>>>(4, nullptr, 1, Wb, out);
}